// round 13
// baseline (speedup 1.0000x reference)
#include <cuda_runtime.h>
#include <cuda_bf16.h>
#include <math.h>

#define B_DIM 32
#define H_DIM 56
#define W_DIM 56
#define C_DIM 256
#define HW (H_DIM * W_DIM)             // 3136
#define NPIX (B_DIM * HW)              // 100352

#define NCHUNK 4
#define IMGS_PER_CHUNK (B_DIM / NCHUNK)          // 8
#define CHUNK_PIX (IMGS_PER_CHUNK * HW)          // 25088
#define CHUNK_F4 (CHUNK_PIX * (C_DIM / 4))       // 1605632

// Scratch (no cudaMalloc allowed).
__device__ float2 g_pooled[NPIX];
__device__ float  g_attn[NPIX];

// ---------------------------------------------------------------------------
// Pool one chunk: 4 pixels/warp, 8 lanes/pixel, 4x 32B loads per lane.
// Grid 784 per chunk; pools run back-to-back on stream 0 -> continuous
// full-width read stream (no inter-chunk ramp).
// ---------------------------------------------------------------------------
struct f8 { float4 a, b; };
__device__ __forceinline__ f8 ldg_f8(const float* p) {
    f8 r;
    unsigned long long d0, d1, d2, d3;
    asm volatile("ld.global.v4.b64 {%0,%1,%2,%3}, [%4];"
                 : "=l"(d0), "=l"(d1), "=l"(d2), "=l"(d3)
                 : "l"(p));
    r.a.x = __uint_as_float((unsigned)(d0));
    r.a.y = __uint_as_float((unsigned)(d0 >> 32));
    r.a.z = __uint_as_float((unsigned)(d1));
    r.a.w = __uint_as_float((unsigned)(d1 >> 32));
    r.b.x = __uint_as_float((unsigned)(d2));
    r.b.y = __uint_as_float((unsigned)(d2 >> 32));
    r.b.z = __uint_as_float((unsigned)(d3));
    r.b.w = __uint_as_float((unsigned)(d3 >> 32));
    return r;
}

__global__ void __launch_bounds__(256) pool_kernel(const float* __restrict__ x,
                                                   int pix_off) {
    int warp = (blockIdx.x * blockDim.x + threadIdx.x) >> 5;
    int lane = threadIdx.x & 31;
    int sub  = lane >> 3;
    int co   = lane & 7;
    int pix  = pix_off + warp * 4 + sub;

    const float* __restrict__ xr = x + (size_t)pix * C_DIM;
    f8 u0 = ldg_f8(xr + co * 8);
    f8 u1 = ldg_f8(xr + co * 8 + 64);
    f8 u2 = ldg_f8(xr + co * 8 + 128);
    f8 u3 = ldg_f8(xr + co * 8 + 192);

    float4 v0 = u0.a, v1 = u0.b, v2 = u1.a, v3 = u1.b;
    float4 v4 = u2.a, v5 = u2.b, v6 = u3.a, v7 = u3.b;

    float s = (((v0.x + v0.y) + (v0.z + v0.w)) + ((v1.x + v1.y) + (v1.z + v1.w)))
            + (((v2.x + v2.y) + (v2.z + v2.w)) + ((v3.x + v3.y) + (v3.z + v3.w)))
            + (((v4.x + v4.y) + (v4.z + v4.w)) + ((v5.x + v5.y) + (v5.z + v5.w)))
            + (((v6.x + v6.y) + (v6.z + v6.w)) + ((v7.x + v7.y) + (v7.z + v7.w)));

    float m01 = fmaxf(fmaxf(fmaxf(v0.x, v0.y), fmaxf(v0.z, v0.w)),
                      fmaxf(fmaxf(v1.x, v1.y), fmaxf(v1.z, v1.w)));
    float m23 = fmaxf(fmaxf(fmaxf(v2.x, v2.y), fmaxf(v2.z, v2.w)),
                      fmaxf(fmaxf(v3.x, v3.y), fmaxf(v3.z, v3.w)));
    float m45 = fmaxf(fmaxf(fmaxf(v4.x, v4.y), fmaxf(v4.z, v4.w)),
                      fmaxf(fmaxf(v5.x, v5.y), fmaxf(v5.z, v5.w)));
    float m67 = fmaxf(fmaxf(fmaxf(v6.x, v6.y), fmaxf(v6.z, v6.w)),
                      fmaxf(fmaxf(v7.x, v7.y), fmaxf(v7.z, v7.w)));
    float m = fmaxf(fmaxf(m01, m23), fmaxf(m45, m67));

    #pragma unroll
    for (int off = 4; off; off >>= 1) {
        s += __shfl_xor_sync(0xffffffffu, s, off);
        m = fmaxf(m, __shfl_xor_sync(0xffffffffu, m, off));
    }

    if (co == 0) {
        g_pooled[pix] = make_float2(s * (1.0f / 256.0f), m);
    }
}

// ---------------------------------------------------------------------------
// Conv one chunk: 7x7 SAME conv + sigmoid -> g_attn. 16x16 tile, smem halo.
// Grid 4x4x8 = 128 blocks, ~1.5us; runs on stream 2, hides under pools.
// ---------------------------------------------------------------------------
__global__ void __launch_bounds__(256) conv_attn_kernel(
    const float* __restrict__ w,     // [7,7,2,1] HWIO
    const float* __restrict__ bias,  // [1]
    int batch_off)
{
    __shared__ float2 tile[22][22];
    __shared__ float  ws[98];
    __shared__ float  bs;

    int bb  = batch_off + blockIdx.z;
    int ty0 = blockIdx.y * 16;
    int tx0 = blockIdx.x * 16;
    int tid = threadIdx.y * 16 + threadIdx.x;

    if (tid < 98) ws[tid] = w[tid];
    if (tid == 127) bs = bias[0];

    const float2* __restrict__ pooled_b = g_pooled + bb * HW;
    #pragma unroll
    for (int i = tid; i < 22 * 22; i += 256) {
        int r = i / 22;
        int c = i - r * 22;
        int yy = ty0 + r - 3;
        int xx = tx0 + c - 3;
        float2 v = make_float2(0.0f, 0.0f);
        if (yy >= 0 && yy < H_DIM && xx >= 0 && xx < W_DIM)
            v = pooled_b[yy * W_DIM + xx];
        tile[r][c] = v;
    }
    __syncthreads();

    int hy = ty0 + threadIdx.y;
    int wx = tx0 + threadIdx.x;
    if (hy < H_DIM && wx < W_DIM) {
        float acc = bs;
        #pragma unroll
        for (int dy = 0; dy < 7; dy++) {
            #pragma unroll
            for (int dx = 0; dx < 7; dx++) {
                float2 p = tile[threadIdx.y + dy][threadIdx.x + dx];
                acc = fmaf(p.x, ws[(dy * 7 + dx) * 2 + 0], acc);
                acc = fmaf(p.y, ws[(dy * 7 + dx) * 2 + 1], acc);
            }
        }
        g_attn[bb * HW + hy * W_DIM + wx] = 1.0f / (1.0f + __expf(-acc));
    }
}

// ---------------------------------------------------------------------------
// Scale one chunk: PURE streaming out = x * attn. 8 float4 per thread,
// block-strided, fully coalesced. x reads are L2-hot (pooled one pipeline
// stage ago). __ldcs last-use / __stcs evict-first writes. Grid 784/chunk.
// ---------------------------------------------------------------------------
__global__ void __launch_bounds__(256) scale_kernel(
    const float* __restrict__ x,
    float* __restrict__ out,
    int f4_off)
{
    int base = f4_off + blockIdx.x * 2048 + threadIdx.x;   // float4 index
    const float4* __restrict__ xr = (const float4*)x;
    float4* __restrict__ o = (float4*)out;

    float4 v[8];
    float  a[8];
    #pragma unroll
    for (int j = 0; j < 8; j++)
        v[j] = __ldcs(&xr[base + j * 256]);
    #pragma unroll
    for (int j = 0; j < 8; j++)
        a[j] = __ldg(&g_attn[(base + j * 256) >> 6]);

    #pragma unroll
    for (int j = 0; j < 8; j++) {
        v[j].x *= a[j]; v[j].y *= a[j]; v[j].z *= a[j]; v[j].w *= a[j];
    }

    #pragma unroll
    for (int j = 0; j < 8; j++)
        __stcs(&o[base + j * 256], v[j]);
}

extern "C" void kernel_launch(void* const* d_in, const int* in_sizes, int n_in,
                              void* d_out, int out_size) {
    const float* x  = (const float*)d_in[0];
    const float* w  = (const float*)d_in[1];
    const float* b  = (const float*)d_in[2];
    float* out = (float*)d_out;

    // Host-side stream/events created once on the first (non-captured) call.
    static cudaStream_t s2 = nullptr;
    static cudaEvent_t evP[NCHUNK];
    static cudaEvent_t evJoin;
    if (s2 == nullptr) {
        cudaStreamCreateWithFlags(&s2, cudaStreamNonBlocking);
        for (int i = 0; i < NCHUNK; i++)
            cudaEventCreateWithFlags(&evP[i], cudaEventDisableTiming);
        cudaEventCreateWithFlags(&evJoin, cudaEventDisableTiming);
    }

    const int pool_blocks  = (CHUNK_PIX / 4) / 8;     // 784
    const int scale_blocks = CHUNK_F4 / 2048;         // 784
    dim3 cgrid(4, 4, IMGS_PER_CHUNK);                 // 128 blocks

    for (int i = 0; i < NCHUNK; i++) {
        // producer chain: pools back-to-back on stream 0 (continuous reads)
        pool_kernel<<<pool_blocks, 256, 0, 0>>>(x, i * CHUNK_PIX);
        cudaEventRecord(evP[i], 0);
        // consumer chain on s2: conv then pure-stream scale, per chunk
        cudaStreamWaitEvent(s2, evP[i], 0);
        conv_attn_kernel<<<cgrid, dim3(16, 16), 0, s2>>>(w, b, i * IMGS_PER_CHUNK);
        scale_kernel<<<scale_blocks, 256, 0, s2>>>(x, out, i * CHUNK_F4);
    }

    cudaEventRecord(evJoin, s2);
    cudaStreamWaitEvent(0, evJoin, 0);
}

// round 14
// speedup vs baseline: 1.1409x; 1.1409x over previous
#include <cuda_runtime.h>
#include <cuda_bf16.h>
#include <math.h>

#define B_DIM 32
#define H_DIM 56
#define W_DIM 56
#define C_DIM 256
#define HW (H_DIM * W_DIM)             // 3136
#define NPIX (B_DIM * HW)              // 100352

#define BAND_ROWS 4
#define BAND_PX (BAND_ROWS * W_DIM)    // 224 pixels per band
#define BANDS_PER_IMG (H_DIM / BAND_ROWS)  // 14
#define NBANDS (B_DIM * BANDS_PER_IMG) // 448
#define BAND_F4 (BAND_PX * (C_DIM/4))  // 14336 float4 per band

#define GRID_CTAS 592                  // 148 SMs x 4 resident
#define LAG_B 148                      // pool-only prefix (bands)
#define MID (LAG_B + 2 * (NBANDS - LAG_B))   // 748
#define NTICKETS (2 * NBANDS)          // 896

// Scratch (no cudaMalloc allowed).
__device__ float2 g_pooled[NPIX];      // band regions are 128B-aligned (1792B)
__device__ int    g_band_done[NBANDS];
__device__ int    g_ticket;

__global__ void reset_kernel() {
    int i = blockIdx.x * blockDim.x + threadIdx.x;
    if (i < NBANDS) g_band_done[i] = 0;
    if (i == 0) g_ticket = 0;
}

struct f8 { float4 a, b; };
__device__ __forceinline__ f8 ldg_f8(const float* p) {
    f8 r;
    unsigned long long d0, d1, d2, d3;
    asm volatile("ld.global.v4.b64 {%0,%1,%2,%3}, [%4];"
                 : "=l"(d0), "=l"(d1), "=l"(d2), "=l"(d3)
                 : "l"(p));
    r.a.x = __uint_as_float((unsigned)(d0));
    r.a.y = __uint_as_float((unsigned)(d0 >> 32));
    r.a.z = __uint_as_float((unsigned)(d1));
    r.a.w = __uint_as_float((unsigned)(d1 >> 32));
    r.b.x = __uint_as_float((unsigned)(d2));
    r.b.y = __uint_as_float((unsigned)(d2 >> 32));
    r.b.z = __uint_as_float((unsigned)(d3));
    r.b.w = __uint_as_float((unsigned)(d3 >> 32));
    return r;
}

// ---------------------------------------------------------------------------
// Interleaved-ticket persistent kernel, band-granular work items.
// Ticket t -> item:
//   t < LAG_B:            pool band t              (pure-read ramp zone)
//   LAG_B <= t < MID:     p=t-LAG_B; even -> pool band LAG_B+p/2
//                                    odd  -> cs   band p/2
//   t >= MID:             cs band (NBANDS-LAG_B)+(t-MID)
// CS band b needs pool bands {b-1,b,b+1} of the same image; their tickets are
// strictly earlier (2(b+1)-2*LAG_B < 2b+1 for all b), pool items are
// wait-free, all CTAs resident -> deadlock-free, spins brief.
// ---------------------------------------------------------------------------
__global__ void __launch_bounds__(256, 4) fused_kernel(
    const float* __restrict__ x,
    const float* __restrict__ w,     // [7,7,2,1] HWIO
    const float* __restrict__ bias,  // [1]
    float* __restrict__ out)
{
    __shared__ int   s_claim;
    __shared__ float attn_s[BAND_PX];
    __shared__ float ws[98];
    __shared__ float bs;

    const int tid  = threadIdx.x;
    const int wid  = tid >> 5;
    const int lane = tid & 31;
    const int sub  = lane >> 3;      // pixel within warp's group of 4
    const int co   = lane & 7;       // 32B slot within pixel

    // one-time per-CTA weight preload
    if (tid < 98) ws[tid] = w[tid];
    if (tid == 104) bs = bias[0];
    __syncthreads();

    for (;;) {
        if (tid == 0) s_claim = atomicAdd(&g_ticket, 1);
        __syncthreads();
        int t = s_claim;
        if (t >= NTICKETS) break;

        int  band;
        bool is_pool;
        if (t < LAG_B) {
            is_pool = true;  band = t;
        } else if (t < MID) {
            int p = t - LAG_B;
            if ((p & 1) == 0) { is_pool = true;  band = LAG_B + (p >> 1); }
            else              { is_pool = false; band = p >> 1; }
        } else {
            is_pool = false; band = (NBANDS - LAG_B) + (t - MID);
        }

        if (is_pool) {
            // ---------------- pool one band (224 pixels) ----------------
            const size_t p0 = (size_t)band * BAND_PX;

            #pragma unroll
            for (int iter = 0; iter < 7; iter++) {
                int pl = iter * 32 + wid * 4 + sub;   // 0..223, no bounds check
                const float* __restrict__ xr = x + (p0 + pl) * C_DIM;
                f8 u0 = ldg_f8(xr + co * 8);
                f8 u1 = ldg_f8(xr + co * 8 + 64);
                f8 u2 = ldg_f8(xr + co * 8 + 128);
                f8 u3 = ldg_f8(xr + co * 8 + 192);

                float4 v0 = u0.a, v1 = u0.b, v2 = u1.a, v3 = u1.b;
                float4 v4 = u2.a, v5 = u2.b, v6 = u3.a, v7 = u3.b;

                float s = (((v0.x+v0.y)+(v0.z+v0.w)) + ((v1.x+v1.y)+(v1.z+v1.w)))
                        + (((v2.x+v2.y)+(v2.z+v2.w)) + ((v3.x+v3.y)+(v3.z+v3.w)))
                        + (((v4.x+v4.y)+(v4.z+v4.w)) + ((v5.x+v5.y)+(v5.z+v5.w)))
                        + (((v6.x+v6.y)+(v6.z+v6.w)) + ((v7.x+v7.y)+(v7.z+v7.w)));

                float m01 = fmaxf(fmaxf(fmaxf(v0.x,v0.y), fmaxf(v0.z,v0.w)),
                                  fmaxf(fmaxf(v1.x,v1.y), fmaxf(v1.z,v1.w)));
                float m23 = fmaxf(fmaxf(fmaxf(v2.x,v2.y), fmaxf(v2.z,v2.w)),
                                  fmaxf(fmaxf(v3.x,v3.y), fmaxf(v3.z,v3.w)));
                float m45 = fmaxf(fmaxf(fmaxf(v4.x,v4.y), fmaxf(v4.z,v4.w)),
                                  fmaxf(fmaxf(v5.x,v5.y), fmaxf(v5.z,v5.w)));
                float m67 = fmaxf(fmaxf(fmaxf(v6.x,v6.y), fmaxf(v6.z,v6.w)),
                                  fmaxf(fmaxf(v7.x,v7.y), fmaxf(v7.z,v7.w)));
                float m = fmaxf(fmaxf(m01, m23), fmaxf(m45, m67));

                #pragma unroll
                for (int off = 4; off; off >>= 1) {
                    s += __shfl_xor_sync(0xffffffffu, s, off);
                    m = fmaxf(m, __shfl_xor_sync(0xffffffffu, m, off));
                }

                if (co == 0)
                    g_pooled[p0 + pl] = make_float2(s * (1.0f / 256.0f), m);
            }

            __syncthreads();
            if (tid == 0) {
                __threadfence();
                atomicExch(&g_band_done[band], 1);
            }
            __syncthreads();
        } else {
            // ------------- conv + sigmoid + scale one band -------------
            int img  = band / BANDS_PER_IMG;
            int bloc = band - img * BANDS_PER_IMG;
            int row0 = bloc * BAND_ROWS;

            // wait for pool bands {band-1, band, band+1} within the image
            if (tid < 3) {
                int nb = band - 1 + tid;
                if (nb >= 0 && nb < NBANDS && nb / BANDS_PER_IMG == img) {
                    volatile int* f = &g_band_done[nb];
                    while (*f == 0) { __nanosleep(64); }
                }
            }
            __syncthreads();
            __threadfence();

            // conv: threads 0..223, one output pixel each
            if (tid < BAND_PX) {
                int r = tid / W_DIM;            // 0..3
                int c = tid - r * W_DIM;        // 0..55
                int gy0 = row0 + r;
                float acc = bs;
                #pragma unroll
                for (int dy = 0; dy < 7; dy++) {
                    int gy = gy0 + dy - 3;
                    if (gy >= 0 && gy < H_DIM) {
                        const float2* prow = g_pooled + (size_t)img * HW + gy * W_DIM;
                        #pragma unroll
                        for (int dx = 0; dx < 7; dx++) {
                            int gx = c + dx - 3;
                            if (gx >= 0 && gx < W_DIM) {
                                float2 p = prow[gx];
                                acc = fmaf(p.x, ws[(dy*7+dx)*2+0], acc);
                                acc = fmaf(p.y, ws[(dy*7+dx)*2+1], acc);
                            }
                        }
                    }
                }
                attn_s[tid] = 1.0f / (1.0f + __expf(-acc));
            }
            __syncthreads();

            // stream the band: 14336 float4, 56 per thread, batches of 8
            const size_t base = (size_t)band * BAND_F4;
            const float4* __restrict__ xr = (const float4*)x;
            float4* __restrict__ o = (float4*)out;

            #pragma unroll
            for (int k = 0; k < 56; k += 8) {
                float4 v[8];
                float  a[8];
                #pragma unroll
                for (int j = 0; j < 8; j++)
                    v[j] = __ldcs(&xr[base + tid + (size_t)(k + j) * 256]);
                #pragma unroll
                for (int j = 0; j < 8; j++)
                    a[j] = attn_s[(tid + (k + j) * 256) >> 6];
                #pragma unroll
                for (int j = 0; j < 8; j++) {
                    v[j].x *= a[j]; v[j].y *= a[j];
                    v[j].z *= a[j]; v[j].w *= a[j];
                }
                #pragma unroll
                for (int j = 0; j < 8; j++)
                    __stcs(&o[base + tid + (size_t)(k + j) * 256], v[j]);
            }
            __syncthreads();
        }
    }
}

extern "C" void kernel_launch(void* const* d_in, const int* in_sizes, int n_in,
                              void* d_out, int out_size) {
    const float* x  = (const float*)d_in[0];
    const float* w  = (const float*)d_in[1];
    const float* b  = (const float*)d_in[2];
    float* out = (float*)d_out;

    reset_kernel<<<2, 256>>>();
    fused_kernel<<<GRID_CTAS, 256>>>(x, w, b, out);
}

// round 15
// speedup vs baseline: 1.4504x; 1.2712x over previous
#include <cuda_runtime.h>
#include <cuda_bf16.h>
#include <math.h>

#define B_DIM 32
#define H_DIM 56
#define W_DIM 56
#define C_DIM 256
#define HW (H_DIM * W_DIM)             // 3136
#define NPIX (B_DIM * HW)              // 100352
#define NROWS (B_DIM * H_DIM)          // 1792 CS rows

#define PPB 32                         // pixels per pool item
#define NPOOL (NPIX / PPB)             // 3136 pool items
#define GROUP 11                       // 7 pool + 4 cs slots per group
#define LAG_G 100                      // cs delayed by 100 groups
#define TOT_G (NPOOL / 7 + LAG_G)      // 548 groups
#define GRID_BLKS (TOT_G * GROUP)      // 6028

// Scratch (no cudaMalloc allowed).
__device__ float2 g_pooled[NPIX];
__device__ int    g_pool_done[NPOOL];

__global__ void reset_kernel() {
    int i = blockIdx.x * blockDim.x + threadIdx.x;
    if (i < NPOOL) g_pool_done[i] = 0;
}

struct f8 { float4 a, b; };
__device__ __forceinline__ f8 ldg_f8(const float* p) {
    f8 r;
    unsigned long long d0, d1, d2, d3;
    asm volatile("ld.global.v4.b64 {%0,%1,%2,%3}, [%4];"
                 : "=l"(d0), "=l"(d1), "=l"(d2), "=l"(d3)
                 : "l"(p));
    r.a.x = __uint_as_float((unsigned)(d0));
    r.a.y = __uint_as_float((unsigned)(d0 >> 32));
    r.a.z = __uint_as_float((unsigned)(d1));
    r.a.w = __uint_as_float((unsigned)(d1 >> 32));
    r.b.x = __uint_as_float((unsigned)(d2));
    r.b.y = __uint_as_float((unsigned)(d2 >> 32));
    r.b.z = __uint_as_float((unsigned)(d3));
    r.b.w = __uint_as_float((unsigned)(d3 >> 32));
    return r;
}

// ---------------------------------------------------------------------------
// One launch; role chosen by blockIdx. Group of 11 consecutive blocks:
//   slot 0..6  -> pool item p = g*7+slot   (32 pixels each; one-shot block)
//   slot 7..10 -> cs row j = (g-LAG_G)*4+(slot-7)  (conv+sigmoid+scale row)
// CS row j's pool deps have dispatch indices ~1100 slots earlier (> resident
// window) -> they are retired before j is dispatched; flags are insurance.
// Blocks do ONE item and exit: HW dispatcher keeps SMs full, read (pool) and
// write (cs) streams interleave chip-wide, x re-read lags pool by ~22MB -> L2.
// ---------------------------------------------------------------------------
__global__ void __launch_bounds__(256) mega_kernel(
    const float* __restrict__ x,
    const float* __restrict__ w,     // [7,7,2,1] HWIO
    const float* __restrict__ bias,  // [1]
    float* __restrict__ out)
{
    const int g    = blockIdx.x / GROUP;
    const int slot = blockIdx.x - g * GROUP;
    const int tid  = threadIdx.x;

    if (slot < 7) {
        // ======================= pool item =======================
        int p = g * 7 + slot;
        if (p >= NPOOL) return;

        const int wid  = tid >> 5;
        const int lane = tid & 31;
        const int sub  = lane >> 3;
        const int co   = lane & 7;
        int pix = p * PPB + wid * 4 + sub;

        const float* __restrict__ xr = x + (size_t)pix * C_DIM;
        f8 u0 = ldg_f8(xr + co * 8);
        f8 u1 = ldg_f8(xr + co * 8 + 64);
        f8 u2 = ldg_f8(xr + co * 8 + 128);
        f8 u3 = ldg_f8(xr + co * 8 + 192);

        float4 v0 = u0.a, v1 = u0.b, v2 = u1.a, v3 = u1.b;
        float4 v4 = u2.a, v5 = u2.b, v6 = u3.a, v7 = u3.b;

        float s = (((v0.x+v0.y)+(v0.z+v0.w)) + ((v1.x+v1.y)+(v1.z+v1.w)))
                + (((v2.x+v2.y)+(v2.z+v2.w)) + ((v3.x+v3.y)+(v3.z+v3.w)))
                + (((v4.x+v4.y)+(v4.z+v4.w)) + ((v5.x+v5.y)+(v5.z+v5.w)))
                + (((v6.x+v6.y)+(v6.z+v6.w)) + ((v7.x+v7.y)+(v7.z+v7.w)));

        float m01 = fmaxf(fmaxf(fmaxf(v0.x,v0.y), fmaxf(v0.z,v0.w)),
                          fmaxf(fmaxf(v1.x,v1.y), fmaxf(v1.z,v1.w)));
        float m23 = fmaxf(fmaxf(fmaxf(v2.x,v2.y), fmaxf(v2.z,v2.w)),
                          fmaxf(fmaxf(v3.x,v3.y), fmaxf(v3.z,v3.w)));
        float m45 = fmaxf(fmaxf(fmaxf(v4.x,v4.y), fmaxf(v4.z,v4.w)),
                          fmaxf(fmaxf(v5.x,v5.y), fmaxf(v5.z,v5.w)));
        float m67 = fmaxf(fmaxf(fmaxf(v6.x,v6.y), fmaxf(v6.z,v6.w)),
                          fmaxf(fmaxf(v7.x,v7.y), fmaxf(v7.z,v7.w)));
        float m = fmaxf(fmaxf(m01, m23), fmaxf(m45, m67));

        #pragma unroll
        for (int off = 4; off; off >>= 1) {
            s += __shfl_xor_sync(0xffffffffu, s, off);
            m = fmaxf(m, __shfl_xor_sync(0xffffffffu, m, off));
        }

        if (co == 0)
            g_pooled[pix] = make_float2(s * (1.0f / 256.0f), m);

        __syncthreads();
        if (tid == 0) {
            __threadfence();
            atomicExch(&g_pool_done[p], 1);
        }
    } else {
        // ================ conv + sigmoid + scale row ================
        if (g < LAG_G) return;
        int j = (g - LAG_G) * 4 + (slot - 7);
        if (j >= NROWS) return;

        __shared__ float attn_s[W_DIM];

        int img = j / H_DIM;
        int row = j - img * H_DIM;

        // pool items covering rows [row-3, row+3] of this image
        int pix_lo = (img * H_DIM + (row > 3 ? row - 3 : 0)) * W_DIM;
        int pix_hi = (img * H_DIM + (row + 3 < H_DIM ? row + 3 : H_DIM - 1)) * W_DIM
                     + W_DIM - 1;
        int p_lo = pix_lo / PPB;
        int p_hi = pix_hi / PPB;          // <= p_lo + 13

        if (tid <= p_hi - p_lo) {
            volatile int* f = &g_pool_done[p_lo + tid];
            while (*f == 0) { __nanosleep(64); }
        }
        __syncthreads();
        __threadfence();

        // conv: threads 0..55, one pixel each (pooled map is L2-hot)
        if (tid < W_DIM) {
            const float2* __restrict__ pooled_b = g_pooled + img * HW;
            float acc = __ldg(bias);
            #pragma unroll
            for (int dy = 0; dy < 7; dy++) {
                int gy = row + dy - 3;
                if (gy >= 0 && gy < H_DIM) {
                    const float2* __restrict__ prow = pooled_b + gy * W_DIM;
                    #pragma unroll
                    for (int dx = 0; dx < 7; dx++) {
                        int gx = tid + dx - 3;
                        if (gx >= 0 && gx < W_DIM) {
                            float2 p = __ldg(&prow[gx]);
                            acc = fmaf(p.x, __ldg(&w[(dy*7+dx)*2+0]), acc);
                            acc = fmaf(p.y, __ldg(&w[(dy*7+dx)*2+1]), acc);
                        }
                    }
                }
            }
            attn_s[tid] = 1.0f / (1.0f + __expf(-acc));
        }
        __syncthreads();

        // stream the row's 3584 float4 (14 per thread, two 7-deep batches)
        const size_t base = ((size_t)img * HW + (size_t)row * W_DIM) * (C_DIM / 4);
        const float4* __restrict__ xr = (const float4*)x;
        float4* __restrict__ o = (float4*)out;

        #pragma unroll
        for (int k = 0; k < 14; k += 7) {
            float4 v[7];
            float  a[7];
            #pragma unroll
            for (int jj = 0; jj < 7; jj++)
                v[jj] = __ldcs(&xr[base + tid + (size_t)(k + jj) * 256]);
            #pragma unroll
            for (int jj = 0; jj < 7; jj++)
                a[jj] = attn_s[(tid + (k + jj) * 256) >> 6];
            #pragma unroll
            for (int jj = 0; jj < 7; jj++) {
                v[jj].x *= a[jj]; v[jj].y *= a[jj];
                v[jj].z *= a[jj]; v[jj].w *= a[jj];
            }
            #pragma unroll
            for (int jj = 0; jj < 7; jj++)
                __stcs(&o[base + tid + (size_t)(k + jj) * 256], v[jj]);
        }
    }
}

extern "C" void kernel_launch(void* const* d_in, const int* in_sizes, int n_in,
                              void* d_out, int out_size) {
    const float* x  = (const float*)d_in[0];
    const float* w  = (const float*)d_in[1];
    const float* b  = (const float*)d_in[2];
    float* out = (float*)d_out;

    reset_kernel<<<(NPOOL + 255) / 256, 256>>>();
    mega_kernel<<<GRID_BLKS, 256>>>(x, w, b, out);
}